// round 1
// baseline (speedup 1.0000x reference)
#include <cuda_runtime.h>
#include <math.h>

// Problem constants (fixed by the dataset)
#define BN_TOTAL 4096      // B*N = 8*512
#define Y_DIM    64
#define C_DIM    256
#define K_TOT    257       // C+1 (y_norm feature appended)
#define PITCH    260       // feat row pitch in floats (257 padded to mult of 4)

// ---- f32x2 packed helpers (Blackwell fma.rn.f32x2: 2x fp32 FMA throughput) ----
__device__ __forceinline__ unsigned long long pk2(float lo, float hi) {
    unsigned long long r;
    asm("mov.b64 %0, {%1, %2};" : "=l"(r) : "f"(lo), "f"(hi));
    return r;
}
__device__ __forceinline__ void ffma2(unsigned long long& d, unsigned long long a, unsigned long long b) {
    asm("fma.rn.f32x2 %0, %1, %2, %0;" : "+l"(d) : "l"(a), "l"(b));
}
__device__ __forceinline__ float2 unpk(unsigned long long a) {
    float2 r;
    asm("mov.b64 {%0, %1}, %2;" : "=f"(r.x), "=f"(r.y) : "l"(a));
    return r;
}

extern __shared__ float smem[];

__global__ __launch_bounds__(512, 1)
void dat_kernel(const float* __restrict__ sampled,   // [4096,64,256]
                const float* __restrict__ valid,     // [4096,64]
                const float* __restrict__ y_norm,    // [64]
                const float* __restrict__ W1,        // [257,256] row-major
                const float* __restrict__ b1,        // [256]
                const float* __restrict__ W2,        // [256]
                const float* __restrict__ b2,        // [1]
                float* __restrict__ out)             // [4096,256]
{
    float* sfeat = smem;                        // [64][PITCH]
    float* spart = smem + Y_DIM * PITCH;        // [16 warps][32]
    float* swt   = spart + 16 * 32;             // [64] final weights

    const int bn   = blockIdx.x;                // token id
    const int tid  = threadIdx.x;               // 0..511
    const int c    = tid & 255;                 // output column
    const int grp  = tid >> 8;                  // y-half: 0 -> y 0..31, 1 -> y 32..63
    const int ybase = grp << 5;
    const int warp = tid >> 5;
    const int lane = tid & 31;

    // ---- stage sampled tile into smem (vectorized, coalesced) ----
    const float4* in4 = reinterpret_cast<const float4*>(sampled) + (size_t)bn * (Y_DIM * C_DIM / 4);
    #pragma unroll
    for (int i = tid; i < Y_DIM * C_DIM / 4; i += 512) {
        int y = i >> 6, j = i & 63;
        float4 v = in4[i];
        *reinterpret_cast<float4*>(&sfeat[y * PITCH + 4 * j]) = v;
    }
    if (tid < Y_DIM) {
        sfeat[tid * PITCH + 256] = y_norm[tid];  // appended depth feature
        sfeat[tid * PITCH + 257] = 0.f;          // zero pad -> branch-free k tail
        sfeat[tid * PITCH + 258] = 0.f;
        sfeat[tid * PITCH + 259] = 0.f;
    }
    __syncthreads();

    // ---- GEMM: h[y][c] = feat[y][:] . W1[:][c]; acc pairs even/odd k in f32x2 ----
    unsigned long long acc[32];
    #pragma unroll
    for (int i = 0; i < 32; ++i) acc[i] = 0ULL;

    // prefetch W1 column values for quad 0
    float w0 = W1[0 * C_DIM + c];
    float w1 = W1[1 * C_DIM + c];
    float w2 = W1[2 * C_DIM + c];
    float w3 = W1[3 * C_DIM + c];

    const float* frow = &sfeat[ybase * PITCH];

    #pragma unroll 1
    for (int q = 0; q < 64; ++q) {
        unsigned long long wp0 = pk2(w0, w1);
        unsigned long long wp1 = pk2(w2, w3);
        if (q < 63) {                            // software prefetch next quad
            int k0n = (q + 1) * 4;
            w0 = W1[(k0n + 0) * C_DIM + c];
            w1 = W1[(k0n + 1) * C_DIM + c];
            w2 = W1[(k0n + 2) * C_DIM + c];
            w3 = W1[(k0n + 3) * C_DIM + c];
        }
        const float* fp = frow + q * 4;
        #pragma unroll
        for (int yy = 0; yy < 32; ++yy) {
            ulonglong2 f = *reinterpret_cast<const ulonglong2*>(fp + yy * PITCH);
            ffma2(acc[yy], f.x, wp0);            // k0,k0+1
            ffma2(acc[yy], f.y, wp1);            // k0+2,k0+3
        }
    }
    // tail: k = 256 (y_norm column); feat col 257 is zero, w hi-lane zero
    {
        float wt_ = W1[256 * C_DIM + c];
        unsigned long long wp0 = pk2(wt_, 0.f);
        const float* fp = frow + 256;
        #pragma unroll
        for (int yy = 0; yy < 32; ++yy) {
            ulonglong2 f = *reinterpret_cast<const ulonglong2*>(fp + yy * PITCH);
            ffma2(acc[yy], f.x, wp0);
        }
    }

    // ---- epilogue: bias + exact GELU + * W2 ----
    const float bb1 = b1[c];
    const float ww2 = W2[c];
    float contrib[32];
    #pragma unroll
    for (int yy = 0; yy < 32; ++yy) {
        float2 p = unpk(acc[yy]);
        float h = p.x + p.y + bb1;
        float g = 0.5f * h * (1.0f + erff(h * 0.70710678118654752f));  // exact GELU
        contrib[yy] = g * ww2;
    }

    // ---- reduce contrib over the 256 c-columns (butterfly + smem partials) ----
    #pragma unroll
    for (int yy = 0; yy < 32; ++yy) {
        float v = contrib[yy];
        v += __shfl_xor_sync(0xffffffffu, v, 16);
        v += __shfl_xor_sync(0xffffffffu, v, 8);
        v += __shfl_xor_sync(0xffffffffu, v, 4);
        v += __shfl_xor_sync(0xffffffffu, v, 2);
        v += __shfl_xor_sync(0xffffffffu, v, 1);
        if (lane == yy) spart[warp * 32 + yy] = v;
    }
    __syncthreads();

    // ---- warp 0: logits -> mask -> softmax -> *valid -> renormalize ----
    if (warp == 0) {
        float lg0 = 0.f, lg1 = 0.f;
        #pragma unroll
        for (int w = 0; w < 8; ++w) {
            lg0 += spart[w * 32 + lane];          // warps 0..7  own y 0..31
            lg1 += spart[(8 + w) * 32 + lane];    // warps 8..15 own y 32..63
        }
        const float bb2 = b2[0];
        lg0 += bb2; lg1 += bb2;
        const float v0 = valid[(size_t)bn * 64 + lane];
        const float v1 = valid[(size_t)bn * 64 + 32 + lane];
        if (v0 < 0.5f) lg0 = -10000.0f;
        if (v1 < 0.5f) lg1 = -10000.0f;

        float m = fmaxf(lg0, lg1);
        #pragma unroll
        for (int s = 16; s > 0; s >>= 1) m = fmaxf(m, __shfl_xor_sync(0xffffffffu, m, s));

        float e0 = expf(lg0 - m), e1 = expf(lg1 - m);
        float z = e0 + e1;
        #pragma unroll
        for (int s = 16; s > 0; s >>= 1) z += __shfl_xor_sync(0xffffffffu, z, s);

        float wt0 = (e0 / z) * v0;
        float wt1 = (e1 / z) * v1;
        float s2 = wt0 + wt1;
        #pragma unroll
        for (int s = 16; s > 0; s >>= 1) s2 += __shfl_xor_sync(0xffffffffu, s2, s);

        const float denom = fmaxf(s2, 1e-6f);
        swt[lane]      = wt0 / denom;
        swt[32 + lane] = wt1 / denom;
    }
    __syncthreads();

    // ---- out[bn][c] = sum_y swt[y] * sampled[y][c] (smem tile reuse) ----
    if (tid < 256) {
        float a = 0.f;
        #pragma unroll
        for (int y = 0; y < Y_DIM; ++y)
            a = fmaf(swt[y], sfeat[y * PITCH + tid], a);
        out[(size_t)bn * C_DIM + tid] = a;
    }
}

extern "C" void kernel_launch(void* const* d_in, const int* in_sizes, int n_in,
                              void* d_out, int out_size) {
    (void)in_sizes; (void)n_in; (void)out_size;
    const int smem_bytes = (Y_DIM * PITCH + 16 * 32 + 64) * (int)sizeof(float);  // 68864
    cudaFuncSetAttribute(dat_kernel, cudaFuncAttributeMaxDynamicSharedMemorySize, smem_bytes);
    dat_kernel<<<BN_TOTAL, 512, smem_bytes>>>(
        (const float*)d_in[0],   // sampled
        (const float*)d_in[1],   // valid
        (const float*)d_in[2],   // y_norm
        (const float*)d_in[3],   // W1
        (const float*)d_in[4],   // b1
        (const float*)d_in[5],   // W2
        (const float*)d_in[6],   // b2
        (float*)d_out);
}

// round 3
// speedup vs baseline: 2.1295x; 2.1295x over previous
#include <cuda_runtime.h>
#include <cuda_bf16.h>
#include <math.h>
#include <stdint.h>

// ==========================================================================
// DepthAwareTokenAggregator via mma.sync bf16 3-pass split (sm_103-safe)
// 4096 tokens, Y=64, C=256, K=257 (padded 288). CTA = 2 tokens (M=128).
// ==========================================================================

#define K_PAD 288
#define S_A   292u                 // A row stride, 32-bit words (mod 32 == 4)
#define STRB  80u                  // B row stride bytes (40 bf16)
#define OFF_B 149504u              // 128 * 292 * 4
#define HALFB 20480u               // 256 * 80  (hi half of a buffer)
#define BUFSZ 40960u               // hi + lo for one k=32 chunk
#define SMEM_TOTAL 231424u         // OFF_B + 2*BUFSZ

__device__ __align__(16) __nv_bfloat16 g_Bhi[256 * K_PAD];
__device__ __align__(16) __nv_bfloat16 g_Blo[256 * K_PAD];

// W1[k][n] -> B[n][k] bf16 hi/lo, zero pad k >= 257
__global__ void prep_B(const float* __restrict__ W1) {
    int n = blockIdx.x, k = threadIdx.x;
    float x = (k < 257) ? W1[(size_t)k * 256 + n] : 0.0f;
    __nv_bfloat16 h = __float2bfloat16_rn(x);
    g_Bhi[n * K_PAD + k] = h;
    g_Blo[n * K_PAD + k] = __float2bfloat16_rn(x - __bfloat162float(h));
}

__device__ __forceinline__ uint32_t smem_u32(const void* p) {
    uint32_t a;
    asm("{ .reg .u64 t; cvta.to.shared.u64 t, %1; cvt.u32.u64 %0, t; }" : "=r"(a) : "l"(p));
    return a;
}
__device__ __forceinline__ uint32_t pack_split(float x) {
    __nv_bfloat16 h = __float2bfloat16_rn(x);
    __nv_bfloat16 l = __float2bfloat16_rn(x - __bfloat162float(h));
    return (uint32_t)__bfloat16_as_ushort(h) | ((uint32_t)__bfloat16_as_ushort(l) << 16);
}
__device__ __forceinline__ void mma16816(float* d, const uint32_t* a, const uint32_t* b) {
    asm volatile("mma.sync.aligned.m16n8k16.row.col.f32.bf16.bf16.f32 "
                 "{%0,%1,%2,%3}, {%4,%5,%6,%7}, {%8,%9}, {%0,%1,%2,%3};"
                 : "+f"(d[0]), "+f"(d[1]), "+f"(d[2]), "+f"(d[3])
                 : "r"(a[0]), "r"(a[1]), "r"(a[2]), "r"(a[3]), "r"(b[0]), "r"(b[1]));
}
__device__ __forceinline__ void ldmat4(uint32_t& r0, uint32_t& r1, uint32_t& r2, uint32_t& r3,
                                       uint32_t addr) {
    asm volatile("ldmatrix.sync.aligned.m8n8.x4.shared.b16 {%0,%1,%2,%3}, [%4];"
                 : "=r"(r0), "=r"(r1), "=r"(r2), "=r"(r3) : "r"(addr));
}
__device__ __forceinline__ float gelu_e(float h) {
    return 0.5f * h * (1.0f + erff(h * 0.70710678118654752f));
}

// Load one k=32 B chunk (hi + lo) into buffer buf via cp.async (all 512 threads).
__device__ __forceinline__ void issue_chunk(uint32_t sbase, int c, int buf) {
    const uint32_t dstb = sbase + OFF_B + (uint32_t)buf * BUFSZ;
    const int tid = threadIdx.x;
    #pragma unroll
    for (int i = 0; i < 4; ++i) {
        int op = i * 512 + tid;                  // 0..2047
        int sel = op >> 10;                      // 0 = hi, 1 = lo
        int rem = op & 1023;
        int n = rem >> 2, q = rem & 3;
        const __nv_bfloat16* g = sel ? g_Blo : g_Bhi;
        const void* src = g + (size_t)n * K_PAD + c * 32 + q * 8;
        uint32_t dst = dstb + (uint32_t)sel * HALFB + (uint32_t)n * STRB + (uint32_t)q * 16u;
        asm volatile("cp.async.cg.shared.global [%0], [%1], 16;" :: "r"(dst), "l"(src));
    }
    asm volatile("cp.async.commit_group;" ::: "memory");
}

extern __shared__ char smem[];

__global__ __launch_bounds__(512, 1)
void dat_hmma_kernel(const float* __restrict__ sampled,   // [4096,64,256]
                     const float* __restrict__ valid,     // [4096,64]
                     const float* __restrict__ y_norm,    // [64]
                     const float* __restrict__ b1,        // [256]
                     const float* __restrict__ W2,        // [256]
                     const float* __restrict__ b2,        // [1]
                     float* __restrict__ out)             // [4096,256]
{
    const uint32_t sbase = smem_u32(smem);
    const int tid = threadIdx.x, wid = tid >> 5, lane = tid & 31;
    const int wm = wid & 3;                      // M-warp: rows wm*32..wm*32+31
    const int wn = wid >> 2;                     // N-warp: cols wn*64..wn*64+63
    const int bx = blockIdx.x;                   // token pair

    // kick off first two B chunks
    issue_chunk(sbase, 0, 0);
    issue_chunk(sbase, 1, 1);

    // ---- A: sampled fp32 -> packed (hi | lo<<16) words in smem ----
    uint32_t* Pw = reinterpret_cast<uint32_t*>(smem);
    const float* src = sampled + (size_t)bx * 128 * 256;
    #pragma unroll
    for (int i = 0; i < 16; ++i) {
        int idx = tid + i * 512;                 // 0..8191 float4 groups
        int row = idx >> 6, kq = idx & 63;
        float4 v = reinterpret_cast<const float4*>(src)[(size_t)row * 64 + kq];
        uint4 w = make_uint4(pack_split(v.x), pack_split(v.y), pack_split(v.z), pack_split(v.w));
        *reinterpret_cast<uint4*>(&Pw[(uint32_t)row * S_A + 4u * kq]) = w;
    }
    // k = 256 (y_norm) and zeros 257..287
    #pragma unroll
    for (int i = 0; i < 2; ++i) {
        int slot = tid + i * 512;                // 0..1023
        int row = slot >> 3, q = slot & 7;
        uint32_t w0 = 0u;
        if (q == 0) w0 = pack_split(y_norm[row & 63]);
        *reinterpret_cast<uint4*>(&Pw[(uint32_t)row * S_A + 256u + 4u * q]) =
            make_uint4(w0, 0u, 0u, 0u);
    }
    __syncthreads();

    // ---- main loop: 9 chunks of k=32, double-buffered B ----
    float acc[2][8][4];
    #pragma unroll
    for (int a = 0; a < 2; ++a)
        #pragma unroll
        for (int b = 0; b < 8; ++b)
            #pragma unroll
            for (int d = 0; d < 4; ++d) acc[a][b][d] = 0.0f;

    #pragma unroll 1
    for (int c = 0; c < 9; ++c) {
        if (c < 8) asm volatile("cp.async.wait_group 1;" ::: "memory");
        else       asm volatile("cp.async.wait_group 0;" ::: "memory");
        __syncthreads();

        const uint32_t bbase = sbase + OFF_B + (uint32_t)(c & 1) * BUFSZ;
        #pragma unroll
        for (int ks = 0; ks < 2; ++ks) {
            // A fragments (hi + lo) for 2 m-tiles
            uint32_t ahi[2][4], alo[2][4];
            #pragma unroll
            for (int mt = 0; mt < 2; ++mt) {
                uint32_t row = (uint32_t)(wm * 32 + mt * 16 + (lane >> 2));
                uint32_t kw = (uint32_t)(c * 32 + ks * 16 + 2 * (lane & 3));
                #pragma unroll
                for (int j = 0; j < 4; ++j) {
                    uint32_t dr = (uint32_t)((j & 1) * 8), dk = (uint32_t)((j >> 1) * 8);
                    uint2 w = *reinterpret_cast<const uint2*>(&Pw[(row + dr) * S_A + kw + dk]);
                    ahi[mt][j] = __byte_perm(w.x, w.y, 0x5410);
                    alo[mt][j] = __byte_perm(w.x, w.y, 0x7632);
                }
            }
            // B lane address pieces
            const uint32_t g = (uint32_t)(lane >> 3);
            const uint32_t nrow = (uint32_t)(wn * 64) + ((g >> 1) * 8u) + (uint32_t)(lane & 7);
            const uint32_t kbyt = ((uint32_t)(ks * 16) + (g & 1) * 8u) * 2u;
            const uint32_t baddr = nrow * STRB + kbyt;

            uint32_t bb[8][2];
            // --- B hi ---
            #pragma unroll
            for (int g2 = 0; g2 < 4; ++g2)
                ldmat4(bb[2 * g2][0], bb[2 * g2][1], bb[2 * g2 + 1][0], bb[2 * g2 + 1][1],
                       bbase + baddr + (uint32_t)g2 * 16u * STRB);
            #pragma unroll
            for (int mt = 0; mt < 2; ++mt)
                #pragma unroll
                for (int nt = 0; nt < 8; ++nt) mma16816(acc[mt][nt], ahi[mt], bb[nt]);
            #pragma unroll
            for (int mt = 0; mt < 2; ++mt)
                #pragma unroll
                for (int nt = 0; nt < 8; ++nt) mma16816(acc[mt][nt], alo[mt], bb[nt]);
            // --- B lo ---
            #pragma unroll
            for (int g2 = 0; g2 < 4; ++g2)
                ldmat4(bb[2 * g2][0], bb[2 * g2][1], bb[2 * g2 + 1][0], bb[2 * g2 + 1][1],
                       bbase + HALFB + baddr + (uint32_t)g2 * 16u * STRB);
            #pragma unroll
            for (int mt = 0; mt < 2; ++mt)
                #pragma unroll
                for (int nt = 0; nt < 8; ++nt) mma16816(acc[mt][nt], ahi[mt], bb[nt]);
        }
        __syncthreads();
        if (c + 2 < 9) issue_chunk(sbase, c + 2, c & 1);
    }

    // ---- epilogue: bias + GELU + W2 dot, per-thread partials ----
    float s0[2] = {0.f, 0.f}, s1[2] = {0.f, 0.f};   // [mt] rows l/4 and l/4+8
    #pragma unroll
    for (int mt = 0; mt < 2; ++mt)
        #pragma unroll
        for (int nt = 0; nt < 8; ++nt) {
            int col = wn * 64 + nt * 8 + 2 * (lane & 3);
            float2 bbv = *reinterpret_cast<const float2*>(&b1[col]);
            float2 wwv = *reinterpret_cast<const float2*>(&W2[col]);
            s0[mt] += gelu_e(acc[mt][nt][0] + bbv.x) * wwv.x;
            s0[mt] += gelu_e(acc[mt][nt][1] + bbv.y) * wwv.y;
            s1[mt] += gelu_e(acc[mt][nt][2] + bbv.x) * wwv.x;
            s1[mt] += gelu_e(acc[mt][nt][3] + bbv.y) * wwv.y;
        }
    #pragma unroll
    for (int mt = 0; mt < 2; ++mt) {
        s0[mt] += __shfl_xor_sync(0xffffffffu, s0[mt], 1);
        s0[mt] += __shfl_xor_sync(0xffffffffu, s0[mt], 2);
        s1[mt] += __shfl_xor_sync(0xffffffffu, s1[mt], 1);
        s1[mt] += __shfl_xor_sync(0xffffffffu, s1[mt], 2);
    }

    float* spart = reinterpret_cast<float*>(smem + OFF_B);          // [4][128]
    float* slog  = spart + 512;                                      // [128]
    float* sval  = slog + 128;                                       // [128]
    float* swts  = sval + 128;                                       // [128]

    __syncthreads();                              // B buffers now reusable
    if ((lane & 3) == 0) {
        int rbase = wm * 32 + (lane >> 2);
        #pragma unroll
        for (int mt = 0; mt < 2; ++mt) {
            spart[wn * 128 + rbase + mt * 16]     = s0[mt];
            spart[wn * 128 + rbase + mt * 16 + 8] = s1[mt];
        }
    }
    if (tid < 128) sval[tid] = valid[(size_t)bx * 128 + tid];
    __syncthreads();

    if (tid < 128) {
        float lg = spart[tid] + spart[128 + tid] + spart[256 + tid] + spart[384 + tid] + b2[0];
        if (sval[tid] < 0.5f) lg = -10000.0f;
        slog[tid] = lg;
    }
    __syncthreads();

    if (wid < 2) {                                // warp w handles token w of the pair
        float l0 = slog[wid * 64 + lane], l1 = slog[wid * 64 + 32 + lane];
        float v0 = sval[wid * 64 + lane], v1 = sval[wid * 64 + 32 + lane];
        float mx = fmaxf(l0, l1);
        #pragma unroll
        for (int s = 16; s > 0; s >>= 1) mx = fmaxf(mx, __shfl_xor_sync(0xffffffffu, mx, s));
        float e0 = expf(l0 - mx), e1 = expf(l1 - mx);
        float z = e0 + e1;
        #pragma unroll
        for (int s = 16; s > 0; s >>= 1) z += __shfl_xor_sync(0xffffffffu, z, s);
        float w0 = (e0 / z) * v0, w1 = (e1 / z) * v1;
        float s2 = w0 + w1;
        #pragma unroll
        for (int s = 16; s > 0; s >>= 1) s2 += __shfl_xor_sync(0xffffffffu, s2, s);
        float denom = fmaxf(s2, 1e-6f);
        swts[wid * 64 + lane]      = w0 / denom;
        swts[wid * 64 + 32 + lane] = w1 / denom;
    }
    __syncthreads();

    // ---- out[token][c] = sum_y w[y] * (hi + lo) from resident packed A ----
    {
        int t = tid >> 8, cc = tid & 255;
        float a = 0.f;
        #pragma unroll 8
        for (int y = 0; y < 64; ++y) {
            uint32_t w = Pw[(uint32_t)(t * 64 + y) * S_A + (uint32_t)cc];
            float v = __bfloat162float(__ushort_as_bfloat16((unsigned short)(w & 0xffffu)))
                    + __bfloat162float(__ushort_as_bfloat16((unsigned short)(w >> 16)));
            a = fmaf(swts[t * 64 + y], v, a);
        }
        out[((size_t)bx * 2 + t) * 256 + cc] = a;
    }
}

extern "C" void kernel_launch(void* const* d_in, const int* in_sizes, int n_in,
                              void* d_out, int out_size) {
    (void)in_sizes; (void)n_in; (void)out_size;
    const float* sampled = (const float*)d_in[0];
    const float* valid   = (const float*)d_in[1];
    const float* y_norm  = (const float*)d_in[2];
    const float* W1      = (const float*)d_in[3];
    const float* b1      = (const float*)d_in[4];
    const float* W2      = (const float*)d_in[5];
    const float* b2      = (const float*)d_in[6];

    prep_B<<<256, K_PAD>>>(W1);

    cudaFuncSetAttribute(dat_hmma_kernel, cudaFuncAttributeMaxDynamicSharedMemorySize, SMEM_TOTAL);
    dat_hmma_kernel<<<2048, 512, SMEM_TOTAL>>>(sampled, valid, y_norm, b1, W2, b2, (float*)d_out);
}

// round 4
// speedup vs baseline: 2.4002x; 1.1271x over previous
#include <cuda_runtime.h>
#include <cuda_bf16.h>
#include <math.h>
#include <stdint.h>

// ==========================================================================
// DepthAwareTokenAggregator via mma.sync bf16 3-pass split (sm_103-safe)
// 4096 tokens, Y=64, C=256, K=257 (padded 288). CTA = 2 tokens (M=128).
// R4: A-conversion pipelined into the MMA mainloop + fast A&S erf epilogue.
// ==========================================================================

#define K_PAD 288
#define S_A   292u                 // A row stride, 32-bit words (mod 32 == 4)
#define STRB  80u                  // B row stride bytes (40 bf16)
#define OFF_B 149504u              // 128 * 292 * 4
#define HALFB 20480u               // 256 * 80  (hi half of a buffer)
#define BUFSZ 40960u               // hi + lo for one k=32 chunk
#define SMEM_TOTAL 231424u         // OFF_B + 2*BUFSZ

__device__ __align__(16) __nv_bfloat16 g_Bhi[256 * K_PAD];
__device__ __align__(16) __nv_bfloat16 g_Blo[256 * K_PAD];

// W1[k][n] -> B[n][k] bf16 hi/lo, zero pad k >= 257
__global__ void prep_B(const float* __restrict__ W1) {
    int n = blockIdx.x, k = threadIdx.x;
    float x = (k < 257) ? W1[(size_t)k * 256 + n] : 0.0f;
    __nv_bfloat16 h = __float2bfloat16_rn(x);
    g_Bhi[n * K_PAD + k] = h;
    g_Blo[n * K_PAD + k] = __float2bfloat16_rn(x - __bfloat162float(h));
}

__device__ __forceinline__ uint32_t smem_u32(const void* p) {
    uint32_t a;
    asm("{ .reg .u64 t; cvta.to.shared.u64 t, %1; cvt.u32.u64 %0, t; }" : "=r"(a) : "l"(p));
    return a;
}
__device__ __forceinline__ uint32_t pack_split(float x) {
    __nv_bfloat16 h = __float2bfloat16_rn(x);
    __nv_bfloat16 l = __float2bfloat16_rn(x - __bfloat162float(h));
    return (uint32_t)__bfloat16_as_ushort(h) | ((uint32_t)__bfloat16_as_ushort(l) << 16);
}
__device__ __forceinline__ void mma16816(float* d, const uint32_t* a, const uint32_t* b) {
    asm volatile("mma.sync.aligned.m16n8k16.row.col.f32.bf16.bf16.f32 "
                 "{%0,%1,%2,%3}, {%4,%5,%6,%7}, {%8,%9}, {%0,%1,%2,%3};"
                 : "+f"(d[0]), "+f"(d[1]), "+f"(d[2]), "+f"(d[3])
                 : "r"(a[0]), "r"(a[1]), "r"(a[2]), "r"(a[3]), "r"(b[0]), "r"(b[1]));
}
__device__ __forceinline__ void ldmat4(uint32_t& r0, uint32_t& r1, uint32_t& r2, uint32_t& r3,
                                       uint32_t addr) {
    asm volatile("ldmatrix.sync.aligned.m8n8.x4.shared.b16 {%0,%1,%2,%3}, [%4];"
                 : "=r"(r0), "=r"(r1), "=r"(r2), "=r"(r3) : "r"(addr));
}
// Exact-enough GELU: Abramowitz-Stegun 7.1.26 erf (|eps| <= 1.5e-7)
__device__ __forceinline__ float gelu_f(float h) {
    float ax = fabsf(h) * 0.70710678118654752f;
    float t  = __fdividef(1.0f, fmaf(0.3275911f, ax, 1.0f));
    float p  = fmaf(t, 1.061405429f, -1.453152027f);
    p = fmaf(t, p, 1.421413741f);
    p = fmaf(t, p, -0.284496736f);
    p = fmaf(t, p, 0.254829592f);
    p = p * t;
    float e  = __expf(-ax * ax);
    float er = copysignf(fmaf(-p, e, 1.0f), h);
    return 0.5f * h * (1.0f + er);
}

// Load one k=32 B chunk (hi + lo) into buffer buf via cp.async (all 512 threads).
__device__ __forceinline__ void issue_chunk(uint32_t sbase, int c, int buf) {
    const uint32_t dstb = sbase + OFF_B + (uint32_t)buf * BUFSZ;
    const int tid = threadIdx.x;
    #pragma unroll
    for (int i = 0; i < 4; ++i) {
        int op = i * 512 + tid;                  // 0..2047
        int sel = op >> 10;                      // 0 = hi, 1 = lo
        int rem = op & 1023;
        int n = rem >> 2, q = rem & 3;
        const __nv_bfloat16* g = sel ? g_Blo : g_Bhi;
        const void* src = g + (size_t)n * K_PAD + c * 32 + q * 8;
        uint32_t dst = dstb + (uint32_t)sel * HALFB + (uint32_t)n * STRB + (uint32_t)q * 16u;
        asm volatile("cp.async.cg.shared.global [%0], [%1], 16;" :: "r"(dst), "l"(src));
    }
    asm volatile("cp.async.commit_group;" ::: "memory");
}

extern __shared__ char smem[];

__global__ __launch_bounds__(512, 1)
void dat_hmma_kernel(const float* __restrict__ sampled,   // [4096,64,256]
                     const float* __restrict__ valid,     // [4096,64]
                     const float* __restrict__ y_norm,    // [64]
                     const float* __restrict__ b1,        // [256]
                     const float* __restrict__ W2,        // [256]
                     const float* __restrict__ b2,        // [1]
                     float* __restrict__ out)             // [4096,256]
{
    const uint32_t sbase = smem_u32(smem);
    const int tid = threadIdx.x, wid = tid >> 5, lane = tid & 31;
    const int wm = wid & 3;                      // M-warp: rows wm*32..wm*32+31
    const int wn = wid >> 2;                     // N-warp: cols wn*64..wn*64+63
    const int bx = blockIdx.x;                   // token pair

    // kick off first two B chunks
    issue_chunk(sbase, 0, 0);
    issue_chunk(sbase, 1, 1);

    uint32_t* Pw = reinterpret_cast<uint32_t*>(smem);
    const float* src = sampled + (size_t)bx * 128 * 256;

    // per-thread A-chunk mapping: row = tid>>2, quads q0 = 2*(tid&3), q0+1
    const int arow = tid >> 2;
    const int aq0  = 2 * (tid & 3);
    const float4* asrc = reinterpret_cast<const float4*>(src + (size_t)arow * 256) + aq0;
    uint32_t* adst = &Pw[(uint32_t)arow * S_A + 4u * (uint32_t)aq0];

    // ---- prologue: convert A chunk 0 only (k 0..31) ----
    {
        float4 v0 = asrc[0], v1 = asrc[1];
        *reinterpret_cast<uint4*>(adst) =
            make_uint4(pack_split(v0.x), pack_split(v0.y), pack_split(v0.z), pack_split(v0.w));
        *reinterpret_cast<uint4*>(adst + 4) =
            make_uint4(pack_split(v1.x), pack_split(v1.y), pack_split(v1.z), pack_split(v1.w));
    }
    // tail chunk 8: k=256 (y_norm) and zeros 257..287
    #pragma unroll
    for (int i = 0; i < 2; ++i) {
        int slot = tid + i * 512;                // 0..1023
        int row = slot >> 3, q = slot & 7;
        uint32_t w0 = 0u;
        if (q == 0) w0 = pack_split(y_norm[row & 63]);
        *reinterpret_cast<uint4*>(&Pw[(uint32_t)row * S_A + 256u + 4u * q]) =
            make_uint4(w0, 0u, 0u, 0u);
    }

    // ---- main loop: 9 chunks of k=32, double-buffered B, pipelined A convert ----
    float acc[2][8][4];
    #pragma unroll
    for (int a = 0; a < 2; ++a)
        #pragma unroll
        for (int b = 0; b < 8; ++b)
            #pragma unroll
            for (int d = 0; d < 4; ++d) acc[a][b][d] = 0.0f;

    #pragma unroll 1
    for (int c = 0; c < 9; ++c) {
        if (c < 8) asm volatile("cp.async.wait_group 1;" ::: "memory");
        else       asm volatile("cp.async.wait_group 0;" ::: "memory");
        __syncthreads();   // B chunk c visible; A chunk c stored (prev iter)

        // prefetch next A chunk's gmem data into registers (hides behind MMA)
        float4 pv0, pv1;
        const bool do_conv = (c < 7);            // converts chunk c+1 (k 32..255)
        if (do_conv) {
            const float4* s = asrc + (size_t)(c + 1) * 8;
            pv0 = s[0]; pv1 = s[1];
        }

        const uint32_t bbase = sbase + OFF_B + (uint32_t)(c & 1) * BUFSZ;
        const uint32_t g = (uint32_t)(lane >> 3);
        const uint32_t nrow = (uint32_t)(wn * 64) + ((g >> 1) * 8u) + (uint32_t)(lane & 7);

        #pragma unroll
        for (int ks = 0; ks < 2; ++ks) {
            // A fragments (hi + lo) for 2 m-tiles
            uint32_t ahi[2][4], alo[2][4];
            #pragma unroll
            for (int mt = 0; mt < 2; ++mt) {
                uint32_t row = (uint32_t)(wm * 32 + mt * 16 + (lane >> 2));
                uint32_t kw = (uint32_t)(c * 32 + ks * 16 + 2 * (lane & 3));
                #pragma unroll
                for (int j = 0; j < 4; ++j) {
                    uint32_t dr = (uint32_t)((j & 1) * 8), dk = (uint32_t)((j >> 1) * 8);
                    uint2 w = *reinterpret_cast<const uint2*>(&Pw[(row + dr) * S_A + kw + dk]);
                    ahi[mt][j] = __byte_perm(w.x, w.y, 0x5410);
                    alo[mt][j] = __byte_perm(w.x, w.y, 0x7632);
                }
            }
            const uint32_t kbyt = ((uint32_t)(ks * 16) + (g & 1) * 8u) * 2u;
            const uint32_t baddr = nrow * STRB + kbyt;

            uint32_t bb[8][2];
            // --- B hi ---
            #pragma unroll
            for (int g2 = 0; g2 < 4; ++g2)
                ldmat4(bb[2 * g2][0], bb[2 * g2][1], bb[2 * g2 + 1][0], bb[2 * g2 + 1][1],
                       bbase + baddr + (uint32_t)g2 * 16u * STRB);
            #pragma unroll
            for (int mt = 0; mt < 2; ++mt)
                #pragma unroll
                for (int nt = 0; nt < 8; ++nt) mma16816(acc[mt][nt], ahi[mt], bb[nt]);
            #pragma unroll
            for (int mt = 0; mt < 2; ++mt)
                #pragma unroll
                for (int nt = 0; nt < 8; ++nt) mma16816(acc[mt][nt], alo[mt], bb[nt]);
            // --- B lo ---
            #pragma unroll
            for (int g2 = 0; g2 < 4; ++g2)
                ldmat4(bb[2 * g2][0], bb[2 * g2][1], bb[2 * g2 + 1][0], bb[2 * g2 + 1][1],
                       bbase + HALFB + baddr + (uint32_t)g2 * 16u * STRB);
            #pragma unroll
            for (int mt = 0; mt < 2; ++mt)
                #pragma unroll
                for (int nt = 0; nt < 8; ++nt) mma16816(acc[mt][nt], ahi[mt], bb[nt]);
        }

        // convert + store next A chunk (regs -> smem)
        if (do_conv) {
            uint32_t* d = adst + (uint32_t)(c + 1) * 32u;
            *reinterpret_cast<uint4*>(d) =
                make_uint4(pack_split(pv0.x), pack_split(pv0.y), pack_split(pv0.z), pack_split(pv0.w));
            *reinterpret_cast<uint4*>(d + 4) =
                make_uint4(pack_split(pv1.x), pack_split(pv1.y), pack_split(pv1.z), pack_split(pv1.w));
        }

        __syncthreads();
        if (c + 2 < 9) issue_chunk(sbase, c + 2, c & 1);
    }

    // ---- epilogue: bias + GELU + W2 dot, per-thread partials ----
    float s0[2] = {0.f, 0.f}, s1[2] = {0.f, 0.f};   // [mt] rows l/4 and l/4+8
    #pragma unroll
    for (int mt = 0; mt < 2; ++mt)
        #pragma unroll
        for (int nt = 0; nt < 8; ++nt) {
            int col = wn * 64 + nt * 8 + 2 * (lane & 3);
            float2 bbv = *reinterpret_cast<const float2*>(&b1[col]);
            float2 wwv = *reinterpret_cast<const float2*>(&W2[col]);
            s0[mt] += gelu_f(acc[mt][nt][0] + bbv.x) * wwv.x;
            s0[mt] += gelu_f(acc[mt][nt][1] + bbv.y) * wwv.y;
            s1[mt] += gelu_f(acc[mt][nt][2] + bbv.x) * wwv.x;
            s1[mt] += gelu_f(acc[mt][nt][3] + bbv.y) * wwv.y;
        }
    #pragma unroll
    for (int mt = 0; mt < 2; ++mt) {
        s0[mt] += __shfl_xor_sync(0xffffffffu, s0[mt], 1);
        s0[mt] += __shfl_xor_sync(0xffffffffu, s0[mt], 2);
        s1[mt] += __shfl_xor_sync(0xffffffffu, s1[mt], 1);
        s1[mt] += __shfl_xor_sync(0xffffffffu, s1[mt], 2);
    }

    float* spart = reinterpret_cast<float*>(smem + OFF_B);          // [4][128]
    float* slog  = spart + 512;                                      // [128]
    float* sval  = slog + 128;                                       // [128]
    float* swts  = sval + 128;                                       // [128]

    __syncthreads();                              // B buffers now reusable
    if ((lane & 3) == 0) {
        int rbase = wm * 32 + (lane >> 2);
        #pragma unroll
        for (int mt = 0; mt < 2; ++mt) {
            spart[wn * 128 + rbase + mt * 16]     = s0[mt];
            spart[wn * 128 + rbase + mt * 16 + 8] = s1[mt];
        }
    }
    if (tid < 128) sval[tid] = valid[(size_t)bx * 128 + tid];
    __syncthreads();

    if (tid < 128) {
        float lg = spart[tid] + spart[128 + tid] + spart[256 + tid] + spart[384 + tid] + b2[0];
        if (sval[tid] < 0.5f) lg = -10000.0f;
        slog[tid] = lg;
    }
    __syncthreads();

    if (wid < 2) {                                // warp w handles token w of the pair
        float l0 = slog[wid * 64 + lane], l1 = slog[wid * 64 + 32 + lane];
        float v0 = sval[wid * 64 + lane], v1 = sval[wid * 64 + 32 + lane];
        float mx = fmaxf(l0, l1);
        #pragma unroll
        for (int s = 16; s > 0; s >>= 1) mx = fmaxf(mx, __shfl_xor_sync(0xffffffffu, mx, s));
        float e0 = expf(l0 - mx), e1 = expf(l1 - mx);
        float z = e0 + e1;
        #pragma unroll
        for (int s = 16; s > 0; s >>= 1) z += __shfl_xor_sync(0xffffffffu, z, s);
        float w0 = (e0 / z) * v0, w1 = (e1 / z) * v1;
        float s2 = w0 + w1;
        #pragma unroll
        for (int s = 16; s > 0; s >>= 1) s2 += __shfl_xor_sync(0xffffffffu, s2, s);
        float denom = fmaxf(s2, 1e-6f);
        swts[wid * 64 + lane]      = w0 / denom;
        swts[wid * 64 + 32 + lane] = w1 / denom;
    }
    __syncthreads();

    // ---- out[token][c] = sum_y w[y] * (hi + lo) from resident packed A ----
    {
        int t = tid >> 8, cc = tid & 255;
        float a = 0.f;
        #pragma unroll 8
        for (int y = 0; y < 64; ++y) {
            uint32_t w = Pw[(uint32_t)(t * 64 + y) * S_A + (uint32_t)cc];
            float v = __bfloat162float(__ushort_as_bfloat16((unsigned short)(w & 0xffffu)))
                    + __bfloat162float(__ushort_as_bfloat16((unsigned short)(w >> 16)));
            a = fmaf(swts[t * 64 + y], v, a);
        }
        out[((size_t)bx * 2 + t) * 256 + cc] = a;
    }
}

extern "C" void kernel_launch(void* const* d_in, const int* in_sizes, int n_in,
                              void* d_out, int out_size) {
    (void)in_sizes; (void)n_in; (void)out_size;
    const float* sampled = (const float*)d_in[0];
    const float* valid   = (const float*)d_in[1];
    const float* y_norm  = (const float*)d_in[2];
    const float* W1      = (const float*)d_in[3];
    const float* b1      = (const float*)d_in[4];
    const float* W2      = (const float*)d_in[5];
    const float* b2      = (const float*)d_in[6];

    prep_B<<<256, K_PAD>>>(W1);

    cudaFuncSetAttribute(dat_hmma_kernel, cudaFuncAttributeMaxDynamicSharedMemorySize, SMEM_TOTAL);
    dat_hmma_kernel<<<2048, 512, SMEM_TOTAL>>>(sampled, valid, y_norm, b1, W2, b2, (float*)d_out);
}

// round 5
// speedup vs baseline: 2.7035x; 1.1264x over previous
#include <cuda_runtime.h>
#include <cuda_bf16.h>
#include <math.h>
#include <stdint.h>

// ==========================================================================
// DepthAwareTokenAggregator via mma.sync bf16 3-pass split (sm_103-safe)
// R5: A hi/lo as separate ldmatrix-fed tiles; y_norm k-slab as fp32 rank-1
//     epilogue update (K = 256 exactly, 8 chunks of 32).
// ==========================================================================

#define SA_E   264u                // A row stride in bf16 elems (528B = 33 granules, odd)
#define SA_B   528u
#define STRB   80u                 // B row stride bytes (odd granule count)
#define OFF_ALO 67584u             // 128 * 528
#define OFF_B   135168u
#define HALFB   20480u             // 256 * 80
#define BUFSZ   40960u
#define OFF_SCR 217088u            // OFF_B + 2*BUFSZ
#define SMEM_TOTAL 222720u

__device__ __align__(16) __nv_bfloat16 g_Bhi[256 * 256];
__device__ __align__(16) __nv_bfloat16 g_Blo[256 * 256];

// W1[k][n] -> B[n][k] bf16 hi/lo for k < 256 (k=256 handled in epilogue)
__global__ void prep_B(const float* __restrict__ W1) {
    int n = blockIdx.x, k = threadIdx.x;
    float x = W1[(size_t)k * 256 + n];
    __nv_bfloat16 h = __float2bfloat16_rn(x);
    g_Bhi[n * 256 + k] = h;
    g_Blo[n * 256 + k] = __float2bfloat16_rn(x - __bfloat162float(h));
}

__device__ __forceinline__ uint32_t smem_u32(const void* p) {
    uint32_t a;
    asm("{ .reg .u64 t; cvta.to.shared.u64 t, %1; cvt.u32.u64 %0, t; }" : "=r"(a) : "l"(p));
    return a;
}
__device__ __forceinline__ void mma16816(float* d, const uint32_t* a, const uint32_t* b) {
    asm volatile("mma.sync.aligned.m16n8k16.row.col.f32.bf16.bf16.f32 "
                 "{%0,%1,%2,%3}, {%4,%5,%6,%7}, {%8,%9}, {%0,%1,%2,%3};"
                 : "+f"(d[0]), "+f"(d[1]), "+f"(d[2]), "+f"(d[3])
                 : "r"(a[0]), "r"(a[1]), "r"(a[2]), "r"(a[3]), "r"(b[0]), "r"(b[1]));
}
__device__ __forceinline__ void ldmat4(uint32_t& r0, uint32_t& r1, uint32_t& r2, uint32_t& r3,
                                       uint32_t addr) {
    asm volatile("ldmatrix.sync.aligned.m8n8.x4.shared.b16 {%0,%1,%2,%3}, [%4];"
                 : "=r"(r0), "=r"(r1), "=r"(r2), "=r"(r3) : "r"(addr));
}
// GELU with Abramowitz-Stegun 7.1.26 erf (|eps| <= 1.5e-7)
__device__ __forceinline__ float gelu_f(float h) {
    float ax = fabsf(h) * 0.70710678118654752f;
    float t  = __fdividef(1.0f, fmaf(0.3275911f, ax, 1.0f));
    float p  = fmaf(t, 1.061405429f, -1.453152027f);
    p = fmaf(t, p, 1.421413741f);
    p = fmaf(t, p, -0.284496736f);
    p = fmaf(t, p, 0.254829592f);
    p = p * t;
    float e  = __expf(-ax * ax);
    float er = copysignf(fmaf(-p, e, 1.0f), h);
    return 0.5f * h * (1.0f + er);
}
// split x into bf16 hi/lo; returns packed pair builders
__device__ __forceinline__ void split8(const float* f, uint32_t* uh, uint32_t* ul) {
    #pragma unroll
    for (int p = 0; p < 4; ++p) {
        __nv_bfloat16 ha = __float2bfloat16_rn(f[2*p]);
        __nv_bfloat16 hb = __float2bfloat16_rn(f[2*p+1]);
        uh[p] = (uint32_t)__bfloat16_as_ushort(ha) |
                ((uint32_t)__bfloat16_as_ushort(hb) << 16);
        __nv_bfloat16 la = __float2bfloat16_rn(f[2*p]   - __bfloat162float(ha));
        __nv_bfloat16 lb = __float2bfloat16_rn(f[2*p+1] - __bfloat162float(hb));
        ul[p] = (uint32_t)__bfloat16_as_ushort(la) |
                ((uint32_t)__bfloat16_as_ushort(lb) << 16);
    }
}

// Load one k=32 B chunk (hi + lo) into buffer buf via cp.async (512 threads).
__device__ __forceinline__ void issue_chunk(uint32_t sbase, int c, int buf) {
    const uint32_t dstb = sbase + OFF_B + (uint32_t)buf * BUFSZ;
    const int tid = threadIdx.x;
    #pragma unroll
    for (int i = 0; i < 4; ++i) {
        int op = i * 512 + tid;                  // 0..2047
        int sel = op >> 10;                      // 0 = hi, 1 = lo
        int rem = op & 1023;
        int n = rem >> 2, q = rem & 3;
        const __nv_bfloat16* g = sel ? g_Blo : g_Bhi;
        const void* src = g + (size_t)n * 256 + c * 32 + q * 8;
        uint32_t dst = dstb + (uint32_t)sel * HALFB + (uint32_t)n * STRB + (uint32_t)q * 16u;
        asm volatile("cp.async.cg.shared.global [%0], [%1], 16;" :: "r"(dst), "l"(src));
    }
    asm volatile("cp.async.commit_group;" ::: "memory");
}

extern __shared__ char smem[];

__global__ __launch_bounds__(512, 1)
void dat_hmma_kernel(const float* __restrict__ sampled,   // [4096,64,256]
                     const float* __restrict__ valid,     // [4096,64]
                     const float* __restrict__ y_norm,    // [64]
                     const float* __restrict__ W1,        // [257,256]
                     const float* __restrict__ b1,        // [256]
                     const float* __restrict__ W2,        // [256]
                     const float* __restrict__ b2,        // [1]
                     float* __restrict__ out)             // [4096,256]
{
    const uint32_t sbase = smem_u32(smem);
    const int tid = threadIdx.x, wid = tid >> 5, lane = tid & 31;
    const int wm = wid & 3;                      // M-warp: rows wm*32..wm*32+31
    const int wn = wid >> 2;                     // N-warp: cols wn*64..wn*64+63
    const int bx = blockIdx.x;                   // token pair

    float* spart = reinterpret_cast<float*>(smem + OFF_SCR);        // [4][128]
    float* slog  = spart + 512;                                      // [128]
    float* sval  = slog + 128;                                       // [128]
    float* swts  = sval + 128;                                       // [128]
    float* sW256 = swts + 128;                                       // [256]
    float* sY    = sW256 + 256;                                      // [128]

    // kick off first two B chunks
    issue_chunk(sbase, 0, 0);
    issue_chunk(sbase, 1, 1);

    const float* src = sampled + (size_t)bx * 128 * 256;
    // per-thread A mapping: row = tid>>2, 8 k-values starting at (tid&3)*8 within chunk
    const int arow = tid >> 2;
    const int aq   = tid & 3;
    const float4* asrc = reinterpret_cast<const float4*>(src + (size_t)arow * 256) + 2 * aq;
    const uint32_t abyte = (uint32_t)arow * SA_B + (uint32_t)aq * 16u;  // 8 bf16 = 16B

    // epilogue constants into scratch (region untouched by mainloop)
    if (tid < 256) sW256[tid] = W1[256 * 256 + tid];
    if (tid < 128) { sY[tid] = y_norm[tid & 63]; sval[tid] = valid[(size_t)bx * 128 + tid]; }

    // ---- prologue: convert A chunk 0 (k 0..31) ----
    {
        float4 v0 = asrc[0], v1 = asrc[1];
        float f[8] = {v0.x, v0.y, v0.z, v0.w, v1.x, v1.y, v1.z, v1.w};
        uint32_t uh[4], ul[4];
        split8(f, uh, ul);
        *reinterpret_cast<uint4*>(smem + abyte)           = make_uint4(uh[0], uh[1], uh[2], uh[3]);
        *reinterpret_cast<uint4*>(smem + OFF_ALO + abyte) = make_uint4(ul[0], ul[1], ul[2], ul[3]);
    }

    // ---- main loop: 8 chunks of k=32, double-buffered B, pipelined A convert ----
    float acc[2][8][4];
    #pragma unroll
    for (int a = 0; a < 2; ++a)
        #pragma unroll
        for (int b = 0; b < 8; ++b)
            #pragma unroll
            for (int d = 0; d < 4; ++d) acc[a][b][d] = 0.0f;

    // ldmatrix lane-offset pieces
    const uint32_t a_lane = (uint32_t)(lane & 15) * SA_B + (uint32_t)(lane >> 4) * 16u;
    const uint32_t g = (uint32_t)(lane >> 3);
    const uint32_t nrow = (uint32_t)(wn * 64) + ((g >> 1) * 8u) + (uint32_t)(lane & 7);

    #pragma unroll 1
    for (int c = 0; c < 8; ++c) {
        if (c < 7) asm volatile("cp.async.wait_group 1;" ::: "memory");
        else       asm volatile("cp.async.wait_group 0;" ::: "memory");
        __syncthreads();   // B chunk c visible; A chunk c stored (prev iter)

        // prefetch next A chunk's gmem floats (hidden behind MMA)
        float4 pv0, pv1;
        const bool do_conv = (c < 7);
        if (do_conv) {
            const float4* s = asrc + (size_t)(c + 1) * 8;
            pv0 = s[0]; pv1 = s[1];
        }

        const uint32_t bbase = sbase + OFF_B + (uint32_t)(c & 1) * BUFSZ;

        #pragma unroll
        for (int ks = 0; ks < 2; ++ks) {
            // A fragments via ldmatrix (hi + lo, 2 m-tiles)
            uint32_t ahi[2][4], alo[2][4];
            #pragma unroll
            for (int mt = 0; mt < 2; ++mt) {
                uint32_t ab = (uint32_t)(wm * 32 + mt * 16) * SA_B
                            + (uint32_t)(c * 32 + ks * 16) * 2u + a_lane;
                ldmat4(ahi[mt][0], ahi[mt][1], ahi[mt][2], ahi[mt][3], sbase + ab);
                ldmat4(alo[mt][0], alo[mt][1], alo[mt][2], alo[mt][3], sbase + OFF_ALO + ab);
            }
            const uint32_t kbyt = ((uint32_t)(ks * 16) + (g & 1) * 8u) * 2u;
            const uint32_t baddr = nrow * STRB + kbyt;

            uint32_t bb[8][2];
            // --- B hi ---
            #pragma unroll
            for (int g2 = 0; g2 < 4; ++g2)
                ldmat4(bb[2 * g2][0], bb[2 * g2][1], bb[2 * g2 + 1][0], bb[2 * g2 + 1][1],
                       bbase + baddr + (uint32_t)g2 * 16u * STRB);
            #pragma unroll
            for (int mt = 0; mt < 2; ++mt)
                #pragma unroll
                for (int nt = 0; nt < 8; ++nt) mma16816(acc[mt][nt], ahi[mt], bb[nt]);
            #pragma unroll
            for (int mt = 0; mt < 2; ++mt)
                #pragma unroll
                for (int nt = 0; nt < 8; ++nt) mma16816(acc[mt][nt], alo[mt], bb[nt]);
            // --- B lo ---
            #pragma unroll
            for (int g2 = 0; g2 < 4; ++g2)
                ldmat4(bb[2 * g2][0], bb[2 * g2][1], bb[2 * g2 + 1][0], bb[2 * g2 + 1][1],
                       bbase + HALFB + baddr + (uint32_t)g2 * 16u * STRB);
            #pragma unroll
            for (int mt = 0; mt < 2; ++mt)
                #pragma unroll
                for (int nt = 0; nt < 8; ++nt) mma16816(acc[mt][nt], ahi[mt], bb[nt]);
        }

        // convert + store next A chunk (regs -> smem)
        if (do_conv) {
            float f[8] = {pv0.x, pv0.y, pv0.z, pv0.w, pv1.x, pv1.y, pv1.z, pv1.w};
            uint32_t uh[4], ul[4];
            split8(f, uh, ul);
            uint32_t d = abyte + (uint32_t)(c + 1) * 64u;
            *reinterpret_cast<uint4*>(smem + d)           = make_uint4(uh[0], uh[1], uh[2], uh[3]);
            *reinterpret_cast<uint4*>(smem + OFF_ALO + d) = make_uint4(ul[0], ul[1], ul[2], ul[3]);
        }

        __syncthreads();
        if (c + 2 < 8) issue_chunk(sbase, c + 2, c & 1);
    }

    // ---- epilogue: fp32 rank-1 y_norm term, bias + GELU + W2 dot ----
    const int r0 = wm * 32 + (lane >> 2);
    float s0[2] = {0.f, 0.f}, s1[2] = {0.f, 0.f};
    #pragma unroll
    for (int mt = 0; mt < 2; ++mt) {
        const float yv0 = sY[r0 + mt * 16];
        const float yv1 = sY[r0 + mt * 16 + 8];
        #pragma unroll
        for (int nt = 0; nt < 8; ++nt) {
            int col = wn * 64 + nt * 8 + 2 * (lane & 3);
            float2 wv  = *reinterpret_cast<const float2*>(&sW256[col]);
            float2 bbv = *reinterpret_cast<const float2*>(&b1[col]);
            float2 wwv = *reinterpret_cast<const float2*>(&W2[col]);
            float h0 = fmaf(yv0, wv.x, acc[mt][nt][0]) + bbv.x;
            float h1 = fmaf(yv0, wv.y, acc[mt][nt][1]) + bbv.y;
            float h2 = fmaf(yv1, wv.x, acc[mt][nt][2]) + bbv.x;
            float h3 = fmaf(yv1, wv.y, acc[mt][nt][3]) + bbv.y;
            s0[mt] += gelu_f(h0) * wwv.x;
            s0[mt] += gelu_f(h1) * wwv.y;
            s1[mt] += gelu_f(h2) * wwv.x;
            s1[mt] += gelu_f(h3) * wwv.y;
        }
    }
    #pragma unroll
    for (int mt = 0; mt < 2; ++mt) {
        s0[mt] += __shfl_xor_sync(0xffffffffu, s0[mt], 1);
        s0[mt] += __shfl_xor_sync(0xffffffffu, s0[mt], 2);
        s1[mt] += __shfl_xor_sync(0xffffffffu, s1[mt], 1);
        s1[mt] += __shfl_xor_sync(0xffffffffu, s1[mt], 2);
    }

    if ((lane & 3) == 0) {
        #pragma unroll
        for (int mt = 0; mt < 2; ++mt) {
            spart[wn * 128 + r0 + mt * 16]     = s0[mt];
            spart[wn * 128 + r0 + mt * 16 + 8] = s1[mt];
        }
    }
    __syncthreads();

    if (tid < 128) {
        float lg = spart[tid] + spart[128 + tid] + spart[256 + tid] + spart[384 + tid] + b2[0];
        if (sval[tid] < 0.5f) lg = -10000.0f;
        slog[tid] = lg;
    }
    __syncthreads();

    if (wid < 2) {                                // warp w handles token w of the pair
        float l0 = slog[wid * 64 + lane], l1 = slog[wid * 64 + 32 + lane];
        float v0 = sval[wid * 64 + lane], v1 = sval[wid * 64 + 32 + lane];
        float mx = fmaxf(l0, l1);
        #pragma unroll
        for (int s = 16; s > 0; s >>= 1) mx = fmaxf(mx, __shfl_xor_sync(0xffffffffu, mx, s));
        float e0 = expf(l0 - mx), e1 = expf(l1 - mx);
        float z = e0 + e1;
        #pragma unroll
        for (int s = 16; s > 0; s >>= 1) z += __shfl_xor_sync(0xffffffffu, z, s);
        float w0 = (e0 / z) * v0, w1 = (e1 / z) * v1;
        float s2 = w0 + w1;
        #pragma unroll
        for (int s = 16; s > 0; s >>= 1) s2 += __shfl_xor_sync(0xffffffffu, s2, s);
        float denom = fmaxf(s2, 1e-6f);
        swts[wid * 64 + lane]      = w0 / denom;
        swts[wid * 64 + 32 + lane] = w1 / denom;
    }
    __syncthreads();

    // ---- out[token][c] = sum_y w[y] * (hi + lo) from resident A tiles ----
    {
        int t = tid >> 8, cc = tid & 255;
        const __nv_bfloat16* Hi = reinterpret_cast<const __nv_bfloat16*>(smem);
        const __nv_bfloat16* Lo = reinterpret_cast<const __nv_bfloat16*>(smem + OFF_ALO);
        float a = 0.f;
        #pragma unroll 8
        for (int y = 0; y < 64; ++y) {
            uint32_t idx = (uint32_t)(t * 64 + y) * SA_E + (uint32_t)cc;
            float v = __bfloat162float(Hi[idx]) + __bfloat162float(Lo[idx]);
            a = fmaf(swts[t * 64 + y], v, a);
        }
        out[((size_t)bx * 2 + t) * 256 + cc] = a;
    }
}

extern "C" void kernel_launch(void* const* d_in, const int* in_sizes, int n_in,
                              void* d_out, int out_size) {
    (void)in_sizes; (void)n_in; (void)out_size;
    const float* sampled = (const float*)d_in[0];
    const float* valid   = (const float*)d_in[1];
    const float* y_norm  = (const float*)d_in[2];
    const float* W1      = (const float*)d_in[3];
    const float* b1      = (const float*)d_in[4];
    const float* W2      = (const float*)d_in[5];
    const float* b2      = (const float*)d_in[6];

    prep_B<<<256, 256>>>(W1);

    cudaFuncSetAttribute(dat_hmma_kernel, cudaFuncAttributeMaxDynamicSharedMemorySize, SMEM_TOTAL);
    dat_hmma_kernel<<<2048, 512, SMEM_TOTAL>>>(sampled, valid, y_norm, W1, b1, W2, b2, (float*)d_out);
}

// round 6
// speedup vs baseline: 3.5571x; 1.3157x over previous
#include <cuda_runtime.h>
#include <cuda_fp16.h>
#include <math.h>
#include <stdint.h>

// ==========================================================================
// DepthAwareTokenAggregator via mma.sync fp16 2-pass split (sm_103-safe)
// R6: A = Ah + Al (fp16 exact-ish), B = Bh only (fp16). C = Ah*Bh + Al*Bh.
//     Dropped term A*Bl ~ 2^-12 rel. Triple-buffered B, 1 barrier/chunk.
// ==========================================================================

#define SA_E   264u                // A row stride in fp16 elems (528B, odd granules)
#define SA_B   528u
#define STRB   80u                 // B row stride bytes (5 granules, odd)
#define OFF_ALO 67584u             // 128 * 528
#define OFF_B   135168u
#define BUFSZ   20480u             // 256 rows * 80B, one k=32 chunk (hi only)
#define OFF_SCR 196608u            // OFF_B + 3*BUFSZ
#define SMEM_TOTAL 201728u

__device__ __align__(16) __half g_Bh[256 * 256];

// W1[k][n] -> Bh[n][k] fp16 for k < 256 (k=256 slab handled in fp32 epilogue)
__global__ void prep_B(const float* __restrict__ W1) {
    int n = blockIdx.x, k = threadIdx.x;
    g_Bh[n * 256 + k] = __float2half_rn(W1[(size_t)k * 256 + n]);
}

__device__ __forceinline__ uint32_t smem_u32(const void* p) {
    uint32_t a;
    asm("{ .reg .u64 t; cvta.to.shared.u64 t, %1; cvt.u32.u64 %0, t; }" : "=r"(a) : "l"(p));
    return a;
}
__device__ __forceinline__ void mma16816(float* d, const uint32_t* a, const uint32_t* b) {
    asm volatile("mma.sync.aligned.m16n8k16.row.col.f32.f16.f16.f32 "
                 "{%0,%1,%2,%3}, {%4,%5,%6,%7}, {%8,%9}, {%0,%1,%2,%3};"
                 : "+f"(d[0]), "+f"(d[1]), "+f"(d[2]), "+f"(d[3])
                 : "r"(a[0]), "r"(a[1]), "r"(a[2]), "r"(a[3]), "r"(b[0]), "r"(b[1]));
}
__device__ __forceinline__ void ldmat4(uint32_t& r0, uint32_t& r1, uint32_t& r2, uint32_t& r3,
                                       uint32_t addr) {
    asm volatile("ldmatrix.sync.aligned.m8n8.x4.shared.b16 {%0,%1,%2,%3}, [%4];"
                 : "=r"(r0), "=r"(r1), "=r"(r2), "=r"(r3) : "r"(addr));
}
// GELU with Abramowitz-Stegun 7.1.26 erf (|eps| <= 1.5e-7)
__device__ __forceinline__ float gelu_f(float h) {
    float ax = fabsf(h) * 0.70710678118654752f;
    float t  = __fdividef(1.0f, fmaf(0.3275911f, ax, 1.0f));
    float p  = fmaf(t, 1.061405429f, -1.453152027f);
    p = fmaf(t, p, 1.421413741f);
    p = fmaf(t, p, -0.284496736f);
    p = fmaf(t, p, 0.254829592f);
    p = p * t;
    float e  = __expf(-ax * ax);
    float er = copysignf(fmaf(-p, e, 1.0f), h);
    return 0.5f * h * (1.0f + er);
}
// split 8 floats into fp16 hi/lo packed pairs
__device__ __forceinline__ void split8(const float* f, uint32_t* uh, uint32_t* ul) {
    #pragma unroll
    for (int p = 0; p < 4; ++p) {
        __half ha = __float2half_rn(f[2*p]);
        __half hb = __float2half_rn(f[2*p+1]);
        uh[p] = (uint32_t)__half_as_ushort(ha) |
                ((uint32_t)__half_as_ushort(hb) << 16);
        __half la = __float2half_rn(f[2*p]   - __half2float(ha));
        __half lb = __float2half_rn(f[2*p+1] - __half2float(hb));
        ul[p] = (uint32_t)__half_as_ushort(la) |
                ((uint32_t)__half_as_ushort(lb) << 16);
    }
}

// Load one k=32 B chunk (hi only) into buffer buf via cp.async (512 threads).
__device__ __forceinline__ void issue_chunk(uint32_t sbase, int c, int buf) {
    const uint32_t dstb = sbase + OFF_B + (uint32_t)buf * BUFSZ;
    const int tid = threadIdx.x;
    #pragma unroll
    for (int i = 0; i < 2; ++i) {
        int op = i * 512 + tid;                  // 0..1023
        int n = op >> 2, q = op & 3;
        const void* src = g_Bh + (size_t)n * 256 + c * 32 + q * 8;
        uint32_t dst = dstb + (uint32_t)n * STRB + (uint32_t)q * 16u;
        asm volatile("cp.async.cg.shared.global [%0], [%1], 16;" :: "r"(dst), "l"(src));
    }
    asm volatile("cp.async.commit_group;" ::: "memory");
}

extern __shared__ char smem[];

__global__ __launch_bounds__(512, 1)
void dat_hmma_kernel(const float* __restrict__ sampled,   // [4096,64,256]
                     const float* __restrict__ valid,     // [4096,64]
                     const float* __restrict__ y_norm,    // [64]
                     const float* __restrict__ W1,        // [257,256]
                     const float* __restrict__ b1,        // [256]
                     const float* __restrict__ W2,        // [256]
                     const float* __restrict__ b2,        // [1]
                     float* __restrict__ out)             // [4096,256]
{
    const uint32_t sbase = smem_u32(smem);
    const int tid = threadIdx.x, wid = tid >> 5, lane = tid & 31;
    const int wm = wid & 3;                      // M-warp: rows wm*32..wm*32+31
    const int wn = wid >> 2;                     // N-warp: cols wn*64..wn*64+63
    const int bx = blockIdx.x;                   // token pair

    float* spart = reinterpret_cast<float*>(smem + OFF_SCR);        // [4][128]
    float* slog  = spart + 512;                                      // [128]
    float* sval  = slog + 128;                                       // [128]
    float* swts  = sval + 128;                                       // [128]
    float* sW256 = swts + 128;                                       // [256]
    float* sY    = sW256 + 256;                                      // [128]

    // kick off first two B chunks (bufs 0, 1)
    issue_chunk(sbase, 0, 0);
    issue_chunk(sbase, 1, 1);

    const float* src = sampled + (size_t)bx * 128 * 256;
    // per-thread A mapping: row = tid>>2, 8 k-values starting at (tid&3)*8 of chunk
    const int arow = tid >> 2;
    const int aq   = tid & 3;
    const float4* asrc = reinterpret_cast<const float4*>(src + (size_t)arow * 256) + 2 * aq;
    const uint32_t abyte = (uint32_t)arow * SA_B + (uint32_t)aq * 16u;  // 8 fp16 = 16B

    // epilogue constants (scratch untouched by mainloop)
    if (tid < 256) sW256[tid] = W1[256 * 256 + tid];
    if (tid < 128) { sY[tid] = y_norm[tid & 63]; sval[tid] = valid[(size_t)bx * 128 + tid]; }

    // ---- prologue: convert A chunk 0 (k 0..31) ----
    {
        float4 v0 = asrc[0], v1 = asrc[1];
        float f[8] = {v0.x, v0.y, v0.z, v0.w, v1.x, v1.y, v1.z, v1.w};
        uint32_t uh[4], ul[4];
        split8(f, uh, ul);
        *reinterpret_cast<uint4*>(smem + abyte)           = make_uint4(uh[0], uh[1], uh[2], uh[3]);
        *reinterpret_cast<uint4*>(smem + OFF_ALO + abyte) = make_uint4(ul[0], ul[1], ul[2], ul[3]);
    }

    // ---- main loop: 8 chunks of k=32, triple-buffered B, one barrier/chunk ----
    float acc[2][8][4];
    #pragma unroll
    for (int a = 0; a < 2; ++a)
        #pragma unroll
        for (int b = 0; b < 8; ++b)
            #pragma unroll
            for (int d = 0; d < 4; ++d) acc[a][b][d] = 0.0f;

    const uint32_t a_lane = (uint32_t)(lane & 15) * SA_B + (uint32_t)(lane >> 4) * 16u;
    const uint32_t g = (uint32_t)(lane >> 3);
    const uint32_t nrow = (uint32_t)(wn * 64) + ((g >> 1) * 8u) + (uint32_t)(lane & 7);

    #pragma unroll 1
    for (int c = 0; c < 8; ++c) {
        if (c < 7) asm volatile("cp.async.wait_group 1;" ::: "memory");
        else       asm volatile("cp.async.wait_group 0;" ::: "memory");
        __syncthreads();   // chunk c visible; A chunk c stored; buf (c+2)%3 retired

        // refill pipeline immediately (buffer (c+2)%3 free as of this barrier)
        if (c + 2 < 8) issue_chunk(sbase, c + 2, (c + 2) % 3);

        // prefetch next A chunk's gmem floats (hidden behind MMA)
        float4 pv0, pv1;
        const bool do_conv = (c < 7);
        if (do_conv) {
            const float4* s = asrc + (size_t)(c + 1) * 8;
            pv0 = s[0]; pv1 = s[1];
        }

        const uint32_t bbase = sbase + OFF_B + (uint32_t)(c % 3) * BUFSZ;

        #pragma unroll
        for (int ks = 0; ks < 2; ++ks) {
            uint32_t ahi[2][4], alo[2][4];
            #pragma unroll
            for (int mt = 0; mt < 2; ++mt) {
                uint32_t ab = (uint32_t)(wm * 32 + mt * 16) * SA_B
                            + (uint32_t)(c * 32 + ks * 16) * 2u + a_lane;
                ldmat4(ahi[mt][0], ahi[mt][1], ahi[mt][2], ahi[mt][3], sbase + ab);
                ldmat4(alo[mt][0], alo[mt][1], alo[mt][2], alo[mt][3], sbase + OFF_ALO + ab);
            }
            const uint32_t kbyt = ((uint32_t)(ks * 16) + (g & 1) * 8u) * 2u;
            const uint32_t baddr = nrow * STRB + kbyt;

            uint32_t bb[8][2];
            #pragma unroll
            for (int g2 = 0; g2 < 4; ++g2)
                ldmat4(bb[2 * g2][0], bb[2 * g2][1], bb[2 * g2 + 1][0], bb[2 * g2 + 1][1],
                       bbase + baddr + (uint32_t)g2 * 16u * STRB);
            #pragma unroll
            for (int mt = 0; mt < 2; ++mt)
                #pragma unroll
                for (int nt = 0; nt < 8; ++nt) mma16816(acc[mt][nt], ahi[mt], bb[nt]);
            #pragma unroll
            for (int mt = 0; mt < 2; ++mt)
                #pragma unroll
                for (int nt = 0; nt < 8; ++nt) mma16816(acc[mt][nt], alo[mt], bb[nt]);
        }

        // convert + store next A chunk (regs -> smem); visible after next barrier
        if (do_conv) {
            float f[8] = {pv0.x, pv0.y, pv0.z, pv0.w, pv1.x, pv1.y, pv1.z, pv1.w};
            uint32_t uh[4], ul[4];
            split8(f, uh, ul);
            uint32_t d = abyte + (uint32_t)(c + 1) * 64u;
            *reinterpret_cast<uint4*>(smem + d)           = make_uint4(uh[0], uh[1], uh[2], uh[3]);
            *reinterpret_cast<uint4*>(smem + OFF_ALO + d) = make_uint4(ul[0], ul[1], ul[2], ul[3]);
        }
    }

    // ---- epilogue: fp32 rank-1 y_norm term, bias + GELU + W2 dot ----
    const int r0 = wm * 32 + (lane >> 2);
    float s0[2] = {0.f, 0.f}, s1[2] = {0.f, 0.f};
    #pragma unroll
    for (int mt = 0; mt < 2; ++mt) {
        const float yv0 = sY[r0 + mt * 16];
        const float yv1 = sY[r0 + mt * 16 + 8];
        #pragma unroll
        for (int nt = 0; nt < 8; ++nt) {
            int col = wn * 64 + nt * 8 + 2 * (lane & 3);
            float2 wv  = *reinterpret_cast<const float2*>(&sW256[col]);
            float2 bbv = *reinterpret_cast<const float2*>(&b1[col]);
            float2 wwv = *reinterpret_cast<const float2*>(&W2[col]);
            float h0 = fmaf(yv0, wv.x, acc[mt][nt][0]) + bbv.x;
            float h1 = fmaf(yv0, wv.y, acc[mt][nt][1]) + bbv.y;
            float h2 = fmaf(yv1, wv.x, acc[mt][nt][2]) + bbv.x;
            float h3 = fmaf(yv1, wv.y, acc[mt][nt][3]) + bbv.y;
            s0[mt] += gelu_f(h0) * wwv.x;
            s0[mt] += gelu_f(h1) * wwv.y;
            s1[mt] += gelu_f(h2) * wwv.x;
            s1[mt] += gelu_f(h3) * wwv.y;
        }
    }
    #pragma unroll
    for (int mt = 0; mt < 2; ++mt) {
        s0[mt] += __shfl_xor_sync(0xffffffffu, s0[mt], 1);
        s0[mt] += __shfl_xor_sync(0xffffffffu, s0[mt], 2);
        s1[mt] += __shfl_xor_sync(0xffffffffu, s1[mt], 1);
        s1[mt] += __shfl_xor_sync(0xffffffffu, s1[mt], 2);
    }

    if ((lane & 3) == 0) {
        #pragma unroll
        for (int mt = 0; mt < 2; ++mt) {
            spart[wn * 128 + r0 + mt * 16]     = s0[mt];
            spart[wn * 128 + r0 + mt * 16 + 8] = s1[mt];
        }
    }
    __syncthreads();

    if (tid < 128) {
        float lg = spart[tid] + spart[128 + tid] + spart[256 + tid] + spart[384 + tid] + b2[0];
        if (sval[tid] < 0.5f) lg = -10000.0f;
        slog[tid] = lg;
    }
    __syncthreads();

    if (wid < 2) {                                // warp w handles token w of the pair
        float l0 = slog[wid * 64 + lane], l1 = slog[wid * 64 + 32 + lane];
        float v0 = sval[wid * 64 + lane], v1 = sval[wid * 64 + 32 + lane];
        float mx = fmaxf(l0, l1);
        #pragma unroll
        for (int s = 16; s > 0; s >>= 1) mx = fmaxf(mx, __shfl_xor_sync(0xffffffffu, mx, s));
        float e0 = expf(l0 - mx), e1 = expf(l1 - mx);
        float z = e0 + e1;
        #pragma unroll
        for (int s = 16; s > 0; s >>= 1) z += __shfl_xor_sync(0xffffffffu, z, s);
        float w0 = (e0 / z) * v0, w1 = (e1 / z) * v1;
        float s2 = w0 + w1;
        #pragma unroll
        for (int s = 16; s > 0; s >>= 1) s2 += __shfl_xor_sync(0xffffffffu, s2, s);
        float denom = fmaxf(s2, 1e-6f);
        swts[wid * 64 + lane]      = w0 / denom;
        swts[wid * 64 + 32 + lane] = w1 / denom;
    }
    __syncthreads();

    // ---- out[token][c] = sum_y w[y] * (hi + lo) from resident A tiles ----
    {
        int t = tid >> 8, cc = tid & 255;
        const __half* Hi = reinterpret_cast<const __half*>(smem);
        const __half* Lo = reinterpret_cast<const __half*>(smem + OFF_ALO);
        float a = 0.f;
        #pragma unroll 8
        for (int y = 0; y < 64; ++y) {
            uint32_t idx = (uint32_t)(t * 64 + y) * SA_E + (uint32_t)cc;
            float v = __half2float(Hi[idx]) + __half2float(Lo[idx]);
            a = fmaf(swts[t * 64 + y], v, a);
        }
        out[((size_t)bx * 2 + t) * 256 + cc] = a;
    }
}

extern "C" void kernel_launch(void* const* d_in, const int* in_sizes, int n_in,
                              void* d_out, int out_size) {
    (void)in_sizes; (void)n_in; (void)out_size;
    const float* sampled = (const float*)d_in[0];
    const float* valid   = (const float*)d_in[1];
    const float* y_norm  = (const float*)d_in[2];
    const float* W1      = (const float*)d_in[3];
    const float* b1      = (const float*)d_in[4];
    const float* W2      = (const float*)d_in[5];
    const float* b2      = (const float*)d_in[6];

    prep_B<<<256, 256>>>(W1);

    cudaFuncSetAttribute(dat_hmma_kernel, cudaFuncAttributeMaxDynamicSharedMemorySize, SMEM_TOTAL);
    dat_hmma_kernel<<<2048, 512, SMEM_TOTAL>>>(sampled, valid, y_norm, W1, b1, W2, b2, (float*)d_out);
}

// round 7
// speedup vs baseline: 4.7155x; 1.3256x over previous
#include <cuda_runtime.h>
#include <cuda_fp16.h>
#include <math.h>
#include <stdint.h>

// ==========================================================================
// DepthAwareTokenAggregator — single-pass fp16 HMMA (sm_103-safe)
// R7: C ≈ fp16(A)·fp16(B) with fp32 accum; y_norm k-slab exact in epilogue.
//     CTA = 1 token (M=64), 256 threads, 2 CTAs/SM. Triple-buffered B.
// ==========================================================================

#define SA_E   264u                // A row stride in fp16 elems (528B, odd granules)
#define SA_B   528u
#define STRB   80u                 // B row stride bytes (5 granules, odd)
#define OFF_B   33792u             // 64 * 528
#define BUFSZ   20480u             // 256 rows * 80B (one k=32 chunk)
#define OFF_SCR 95232u             // OFF_B + 3*BUFSZ
#define SMEM_TOTAL 98304u          // 96 KB -> 2 CTAs/SM

__device__ __align__(16) __half g_Bh[256 * 256];

// W1[k][n] -> Bh[n][k] fp16 for k < 256 (k=256 slab handled in fp32 epilogue)
__global__ void prep_B(const float* __restrict__ W1) {
    int n = blockIdx.x, k = threadIdx.x;
    g_Bh[n * 256 + k] = __float2half_rn(W1[(size_t)k * 256 + n]);
}

__device__ __forceinline__ uint32_t smem_u32(const void* p) {
    uint32_t a;
    asm("{ .reg .u64 t; cvta.to.shared.u64 t, %1; cvt.u32.u64 %0, t; }" : "=r"(a) : "l"(p));
    return a;
}
__device__ __forceinline__ void mma16816(float* d, const uint32_t* a, const uint32_t* b) {
    asm volatile("mma.sync.aligned.m16n8k16.row.col.f32.f16.f16.f32 "
                 "{%0,%1,%2,%3}, {%4,%5,%6,%7}, {%8,%9}, {%0,%1,%2,%3};"
                 : "+f"(d[0]), "+f"(d[1]), "+f"(d[2]), "+f"(d[3])
                 : "r"(a[0]), "r"(a[1]), "r"(a[2]), "r"(a[3]), "r"(b[0]), "r"(b[1]));
}
__device__ __forceinline__ void ldmat4(uint32_t& r0, uint32_t& r1, uint32_t& r2, uint32_t& r3,
                                       uint32_t addr) {
    asm volatile("ldmatrix.sync.aligned.m8n8.x4.shared.b16 {%0,%1,%2,%3}, [%4];"
                 : "=r"(r0), "=r"(r1), "=r"(r2), "=r"(r3) : "r"(addr));
}
// GELU with Abramowitz-Stegun 7.1.26 erf (|eps| <= 1.5e-7)
__device__ __forceinline__ float gelu_f(float h) {
    float ax = fabsf(h) * 0.70710678118654752f;
    float t  = __fdividef(1.0f, fmaf(0.3275911f, ax, 1.0f));
    float p  = fmaf(t, 1.061405429f, -1.453152027f);
    p = fmaf(t, p, 1.421413741f);
    p = fmaf(t, p, -0.284496736f);
    p = fmaf(t, p, 0.254829592f);
    p = p * t;
    float e  = __expf(-ax * ax);
    float er = copysignf(fmaf(-p, e, 1.0f), h);
    return 0.5f * h * (1.0f + er);
}
// convert 8 floats to packed fp16 pairs
__device__ __forceinline__ void cvt8(const float* f, uint32_t* uh) {
    #pragma unroll
    for (int p = 0; p < 4; ++p) {
        __half ha = __float2half_rn(f[2*p]);
        __half hb = __float2half_rn(f[2*p+1]);
        uh[p] = (uint32_t)__half_as_ushort(ha) |
                ((uint32_t)__half_as_ushort(hb) << 16);
    }
}

// Load one k=32 B chunk into buffer buf via cp.async (256 threads).
__device__ __forceinline__ void issue_chunk(uint32_t sbase, int c, int buf) {
    const uint32_t dstb = sbase + OFF_B + (uint32_t)buf * BUFSZ;
    const int tid = threadIdx.x;
    #pragma unroll
    for (int i = 0; i < 4; ++i) {
        int op = i * 256 + tid;                  // 0..1023
        int n = op >> 2, q = op & 3;
        const void* src = g_Bh + (size_t)n * 256 + c * 32 + q * 8;
        uint32_t dst = dstb + (uint32_t)n * STRB + (uint32_t)q * 16u;
        asm volatile("cp.async.cg.shared.global [%0], [%1], 16;" :: "r"(dst), "l"(src));
    }
    asm volatile("cp.async.commit_group;" ::: "memory");
}

extern __shared__ char smem[];

__global__ __launch_bounds__(256, 2)
void dat_hmma_kernel(const float* __restrict__ sampled,   // [4096,64,256]
                     const float* __restrict__ valid,     // [4096,64]
                     const float* __restrict__ y_norm,    // [64]
                     const float* __restrict__ W1,        // [257,256]
                     const float* __restrict__ b1,        // [256]
                     const float* __restrict__ W2,        // [256]
                     const float* __restrict__ b2,        // [1]
                     float* __restrict__ out)             // [4096,256]
{
    const uint32_t sbase = smem_u32(smem);
    const int tid = threadIdx.x, wid = tid >> 5, lane = tid & 31;
    const int wm = wid & 1;                      // M-warp: rows wm*32..wm*32+31
    const int wn = wid >> 1;                     // N-warp: cols wn*64..wn*64+63
    const int bx = blockIdx.x;                   // token id

    float* spart = reinterpret_cast<float*>(smem + OFF_SCR);        // [4][64]
    float* slog  = spart + 256;                                      // [64]
    float* sval  = slog + 64;                                        // [64]
    float* swts  = sval + 64;                                        // [64]
    float* sW256 = swts + 64;                                        // [256]
    float* sY    = sW256 + 256;                                      // [64]

    // kick off first two B chunks (bufs 0, 1)
    issue_chunk(sbase, 0, 0);
    issue_chunk(sbase, 1, 1);

    const float* src = sampled + (size_t)bx * 64 * 256;
    // per-thread A mapping: row = tid>>2 (0..63), 8 k-values at (tid&3)*8 of chunk
    const int arow = tid >> 2;
    const int aq   = tid & 3;
    const float4* asrc = reinterpret_cast<const float4*>(src + (size_t)arow * 256) + 2 * aq;
    const uint32_t abyte = (uint32_t)arow * SA_B + (uint32_t)aq * 16u;  // 8 fp16 = 16B

    // epilogue constants (scratch untouched by mainloop)
    sW256[tid] = W1[256 * 256 + tid];
    if (tid < 64) { sY[tid] = y_norm[tid]; sval[tid] = valid[(size_t)bx * 64 + tid]; }

    // ---- prologue: convert A chunk 0 (k 0..31) ----
    {
        float4 v0 = asrc[0], v1 = asrc[1];
        float f[8] = {v0.x, v0.y, v0.z, v0.w, v1.x, v1.y, v1.z, v1.w};
        uint32_t uh[4];
        cvt8(f, uh);
        *reinterpret_cast<uint4*>(smem + abyte) = make_uint4(uh[0], uh[1], uh[2], uh[3]);
    }

    // ---- main loop: 8 chunks of k=32, triple-buffered B, one barrier/chunk ----
    float acc[2][8][4];
    #pragma unroll
    for (int a = 0; a < 2; ++a)
        #pragma unroll
        for (int b = 0; b < 8; ++b)
            #pragma unroll
            for (int d = 0; d < 4; ++d) acc[a][b][d] = 0.0f;

    const uint32_t a_lane = (uint32_t)(lane & 15) * SA_B + (uint32_t)(lane >> 4) * 16u;
    const uint32_t g = (uint32_t)(lane >> 3);
    const uint32_t nrow = (uint32_t)(wn * 64) + ((g >> 1) * 8u) + (uint32_t)(lane & 7);

    #pragma unroll 1
    for (int c = 0; c < 8; ++c) {
        if (c < 7) asm volatile("cp.async.wait_group 1;" ::: "memory");
        else       asm volatile("cp.async.wait_group 0;" ::: "memory");
        __syncthreads();   // chunk c visible; A chunk c stored; buf (c+2)%3 retired

        // refill pipeline (buffer (c+2)%3 free as of this barrier)
        if (c + 2 < 8) issue_chunk(sbase, c + 2, (c + 2) % 3);

        // prefetch next A chunk's gmem floats (hidden behind MMA)
        float4 pv0, pv1;
        const bool do_conv = (c < 7);
        if (do_conv) {
            const float4* s = asrc + (size_t)(c + 1) * 8;
            pv0 = s[0]; pv1 = s[1];
        }

        const uint32_t bbase = sbase + OFF_B + (uint32_t)(c % 3) * BUFSZ;

        #pragma unroll
        for (int ks = 0; ks < 2; ++ks) {
            uint32_t ah[2][4];
            #pragma unroll
            for (int mt = 0; mt < 2; ++mt) {
                uint32_t ab = (uint32_t)(wm * 32 + mt * 16) * SA_B
                            + (uint32_t)(c * 32 + ks * 16) * 2u + a_lane;
                ldmat4(ah[mt][0], ah[mt][1], ah[mt][2], ah[mt][3], sbase + ab);
            }
            const uint32_t kbyt = ((uint32_t)(ks * 16) + (g & 1) * 8u) * 2u;
            const uint32_t baddr = nrow * STRB + kbyt;

            uint32_t bb[8][2];
            #pragma unroll
            for (int g2 = 0; g2 < 4; ++g2)
                ldmat4(bb[2 * g2][0], bb[2 * g2][1], bb[2 * g2 + 1][0], bb[2 * g2 + 1][1],
                       bbase + baddr + (uint32_t)g2 * 16u * STRB);
            #pragma unroll
            for (int mt = 0; mt < 2; ++mt)
                #pragma unroll
                for (int nt = 0; nt < 8; ++nt) mma16816(acc[mt][nt], ah[mt], bb[nt]);
        }

        // convert + store next A chunk (regs -> smem); visible after next barrier
        if (do_conv) {
            float f[8] = {pv0.x, pv0.y, pv0.z, pv0.w, pv1.x, pv1.y, pv1.z, pv1.w};
            uint32_t uh[4];
            cvt8(f, uh);
            *reinterpret_cast<uint4*>(smem + abyte + (uint32_t)(c + 1) * 64u) =
                make_uint4(uh[0], uh[1], uh[2], uh[3]);
        }
    }

    // ---- epilogue: fp32 rank-1 y_norm term, bias + GELU + W2 dot ----
    const int r0 = wm * 32 + (lane >> 2);
    float s0[2] = {0.f, 0.f}, s1[2] = {0.f, 0.f};
    #pragma unroll
    for (int mt = 0; mt < 2; ++mt) {
        const float yv0 = sY[r0 + mt * 16];
        const float yv1 = sY[r0 + mt * 16 + 8];
        #pragma unroll
        for (int nt = 0; nt < 8; ++nt) {
            int col = wn * 64 + nt * 8 + 2 * (lane & 3);
            float2 wv  = *reinterpret_cast<const float2*>(&sW256[col]);
            float2 bbv = *reinterpret_cast<const float2*>(&b1[col]);
            float2 wwv = *reinterpret_cast<const float2*>(&W2[col]);
            float h0 = fmaf(yv0, wv.x, acc[mt][nt][0]) + bbv.x;
            float h1 = fmaf(yv0, wv.y, acc[mt][nt][1]) + bbv.y;
            float h2 = fmaf(yv1, wv.x, acc[mt][nt][2]) + bbv.x;
            float h3 = fmaf(yv1, wv.y, acc[mt][nt][3]) + bbv.y;
            s0[mt] += gelu_f(h0) * wwv.x;
            s0[mt] += gelu_f(h1) * wwv.y;
            s1[mt] += gelu_f(h2) * wwv.x;
            s1[mt] += gelu_f(h3) * wwv.y;
        }
    }
    #pragma unroll
    for (int mt = 0; mt < 2; ++mt) {
        s0[mt] += __shfl_xor_sync(0xffffffffu, s0[mt], 1);
        s0[mt] += __shfl_xor_sync(0xffffffffu, s0[mt], 2);
        s1[mt] += __shfl_xor_sync(0xffffffffu, s1[mt], 1);
        s1[mt] += __shfl_xor_sync(0xffffffffu, s1[mt], 2);
    }

    if ((lane & 3) == 0) {
        #pragma unroll
        for (int mt = 0; mt < 2; ++mt) {
            spart[wn * 64 + r0 + mt * 16]     = s0[mt];
            spart[wn * 64 + r0 + mt * 16 + 8] = s1[mt];
        }
    }
    __syncthreads();

    if (tid < 64) {
        float lg = spart[tid] + spart[64 + tid] + spart[128 + tid] + spart[192 + tid] + b2[0];
        if (sval[tid] < 0.5f) lg = -10000.0f;
        slog[tid] = lg;
    }
    __syncthreads();

    if (wid == 0) {                               // softmax over 64 y for this token
        float l0 = slog[lane], l1 = slog[32 + lane];
        float v0 = sval[lane], v1 = sval[32 + lane];
        float mx = fmaxf(l0, l1);
        #pragma unroll
        for (int s = 16; s > 0; s >>= 1) mx = fmaxf(mx, __shfl_xor_sync(0xffffffffu, mx, s));
        float e0 = expf(l0 - mx), e1 = expf(l1 - mx);
        float z = e0 + e1;
        #pragma unroll
        for (int s = 16; s > 0; s >>= 1) z += __shfl_xor_sync(0xffffffffu, z, s);
        float w0 = (e0 / z) * v0, w1 = (e1 / z) * v1;
        float s2 = w0 + w1;
        #pragma unroll
        for (int s = 16; s > 0; s >>= 1) s2 += __shfl_xor_sync(0xffffffffu, s2, s);
        float denom = fmaxf(s2, 1e-6f);
        swts[lane]      = w0 / denom;
        swts[32 + lane] = w1 / denom;
    }
    __syncthreads();

    // ---- out[bx][c] = sum_y w[y] * A_hi[y][c] from resident tile ----
    {
        const __half* Hi = reinterpret_cast<const __half*>(smem);
        float a = 0.f;
        #pragma unroll 8
        for (int y = 0; y < 64; ++y)
            a = fmaf(swts[y], __half2float(Hi[(uint32_t)y * SA_E + (uint32_t)tid]), a);
        out[(size_t)bx * 256 + tid] = a;
    }
}

extern "C" void kernel_launch(void* const* d_in, const int* in_sizes, int n_in,
                              void* d_out, int out_size) {
    (void)in_sizes; (void)n_in; (void)out_size;
    const float* sampled = (const float*)d_in[0];
    const float* valid   = (const float*)d_in[1];
    const float* y_norm  = (const float*)d_in[2];
    const float* W1      = (const float*)d_in[3];
    const float* b1      = (const float*)d_in[4];
    const float* W2      = (const float*)d_in[5];
    const float* b2      = (const float*)d_in[6];

    prep_B<<<256, 256>>>(W1);

    cudaFuncSetAttribute(dat_hmma_kernel, cudaFuncAttributeMaxDynamicSharedMemorySize, SMEM_TOTAL);
    dat_hmma_kernel<<<4096, 256, SMEM_TOTAL>>>(sampled, valid, y_norm, W1, b1, W2, b2, (float*)d_out);
}